// round 4
// baseline (speedup 1.0000x reference)
#include <cuda_runtime.h>
#include <cuda_bf16.h>

// out[k][d] = mult_k * sum_i W_k[eb_input[i]][d]   (offsets mathematically dead:
// every index position lands in some bag and all bags are summed).
//
// hist: 1 packed u16 global RED per index (L2-atomic-ALU bound, ~floor).
// sweep: weighted streaming reduction; tables stay L2-resident across graph
// replays (72MB + scratch < 126MB L2), so keep default (fill) cache policy.

#define MAX_EMB 2000000
#define CNT_WORDS ((MAX_EMB + 1) / 2)

// Packed counts: word w = u16 counts of rows 2w (low) and 2w+1 (high).
// Zeroed at load; sweep re-zeroes after reading -> clean state every replay.
__device__ unsigned int g_cnt[CNT_WORDS];
// 9 double accumulators padded to 512B stride (distinct L2 slices).
__device__ double g_acc[9 * 64];
__device__ unsigned int g_done;   // last-block ticket, reset each replay

// ---------------------------------------------------------------------------
// Kernel 1: histogram. int2 (2 indices) per thread, 2 packed REDs.
// ---------------------------------------------------------------------------
__global__ void k_hist(const int* __restrict__ idx, int n_idx) {
    int t = blockIdx.x * blockDim.x + threadIdx.x;
    int n2 = n_idx >> 1;
    if (t < n2) {
        int2 a = __ldcs((const int2*)idx + t);   // index stream: evict-first
        atomicAdd(&g_cnt[a.x >> 1], 1u << ((a.x & 1) << 4));
        atomicAdd(&g_cnt[a.y >> 1], 1u << ((a.y & 1) << 4));
    }
    if (blockIdx.x == 0 && threadIdx.x == 0 && (n_idx & 1)) {
        int r = idx[n_idx - 1];
        atomicAdd(&g_cnt[r >> 1], 1u << ((r & 1) << 4));
    }
}

// ---------------------------------------------------------------------------
// Kernel 2: weighted sweep + fused finalize.
// Each thread: 4 rows (3x float4 per table), one u64 count read + one 8B zero.
// ---------------------------------------------------------------------------
__global__ void k_sweep(const float* __restrict__ W0,
                        const float* __restrict__ W1,
                        const float* __restrict__ W2,
                        int num_emb, float* __restrict__ out,
                        unsigned int nblocks) {
    int t = blockIdx.x * blockDim.x + threadIdx.x;
    int r0 = t * 4;

    float acc[9];
#pragma unroll
    for (int k = 0; k < 9; k++) acc[k] = 0.0f;

    if (r0 + 4 <= num_emb) {
        unsigned long long* cw = (unsigned long long*)&g_cnt[r0 >> 1];
        unsigned long long c = *cw;
        *cw = 0ULL;                                   // re-init for next replay
        float c0 = (float)( c        & 0xFFFFu);
        float c1 = (float)((c >> 16) & 0xFFFFu);
        float c2 = (float)((c >> 32) & 0xFFFFu);
        float c3 = (float)((c >> 48) & 0xFFFFu);

        const float* Ws[3] = {W0, W1, W2};
#pragma unroll
        for (int k = 0; k < 3; k++) {
            const float4* Wv = (const float4*)Ws[k] + 3 * t;   // 12 floats = 4 rows
            float4 a = __ldg(Wv + 0);
            float4 b = __ldg(Wv + 1);
            float4 d = __ldg(Wv + 2);
            // rows: r0: a.x a.y a.z | r0+1: a.w b.x b.y | r0+2: b.z b.w d.x | r0+3: d.y d.z d.w
            acc[3 * k + 0] += c0 * a.x + c1 * a.w + c2 * b.z + c3 * d.y;
            acc[3 * k + 1] += c0 * a.y + c1 * b.x + c2 * b.w + c3 * d.z;
            acc[3 * k + 2] += c0 * a.z + c1 * b.y + c2 * d.x + c3 * d.w;
        }
    } else if (r0 < num_emb) {
        for (int r = r0; r < num_emb; r++) {
            unsigned int w = g_cnt[r >> 1];
            float c = (float)((w >> ((r & 1) << 4)) & 0xFFFFu);
            if ((r & 1) || r + 1 >= num_emb) g_cnt[r >> 1] = 0u;
            const float* Ws[3] = {W0, W1, W2};
#pragma unroll
            for (int k = 0; k < 3; k++) {
                acc[3 * k + 0] += c * Ws[k][3 * r + 0];
                acc[3 * k + 1] += c * Ws[k][3 * r + 1];
                acc[3 * k + 2] += c * Ws[k][3 * r + 2];
            }
        }
    }

    // warp reduction
    unsigned lane = threadIdx.x & 31u;
    unsigned warp = threadIdx.x >> 5;
#pragma unroll
    for (int k = 0; k < 9; k++) {
#pragma unroll
        for (int o = 16; o > 0; o >>= 1)
            acc[k] += __shfl_down_sync(0xffffffffu, acc[k], o);
    }

    __shared__ float s_red[8][9];
    __shared__ bool s_last;
    if (lane == 0) {
#pragma unroll
        for (int k = 0; k < 9; k++) s_red[warp][k] = acc[k];
    }
    __syncthreads();

    if (threadIdx.x < 9) {
        double s = 0.0;
#pragma unroll
        for (int w = 0; w < 8; w++) s += (double)s_red[w][threadIdx.x];
        atomicAdd(&g_acc[threadIdx.x * 64], s);
    }
    __threadfence();
    __syncthreads();

    if (threadIdx.x == 0)
        s_last = (atomicAdd(&g_done, 1u) == nblocks - 1);
    __syncthreads();

    if (s_last) {
        if (threadIdx.x < 9) {
            const float mult[3] = {5.0f, 10.0f, 6.0f};
            double v = g_acc[threadIdx.x * 64];
            g_acc[threadIdx.x * 64] = 0.0;           // reset for next replay
            out[threadIdx.x] = (float)((double)mult[threadIdx.x / 3] * v);
        }
        if (threadIdx.x == 0) g_done = 0u;           // reset ticket
    }
}

// ---------------------------------------------------------------------------
extern "C" void kernel_launch(void* const* d_in, const int* in_sizes, int n_in,
                              void* d_out, int out_size) {
    const int*   idx = (const int*)d_in[0];
    // d_in[1] = eb_offset : mathematically unused
    const float* W0  = (const float*)d_in[2];
    const float* W1  = (const float*)d_in[3];
    const float* W2  = (const float*)d_in[4];
    int n_idx   = in_sizes[0];
    int num_emb = in_sizes[2] / 3;

    int n2 = n_idx >> 1;
    int hist_blocks = (n2 + 255) / 256;
    if (hist_blocks < 1) hist_blocks = 1;
    k_hist<<<hist_blocks, 256>>>(idx, n_idx);

    int sweep_threads = (num_emb + 3) / 4;
    int sweep_blocks = (sweep_threads + 255) / 256;
    if (sweep_blocks < 1) sweep_blocks = 1;
    k_sweep<<<sweep_blocks, 256>>>(W0, W1, W2, num_emb, (float*)d_out,
                                   (unsigned int)sweep_blocks);
}